// round 5
// baseline (speedup 1.0000x reference)
#include <cuda_runtime.h>
#include <math.h>

#define NNODES   100000
#define NEDGES   1600000
#define F_IN     128
#define F_HID    64
#define N_GRAPHS 128
#define BUCKET   64   // max in-degree capacity (Poisson(16): P(>=64) ~ 1e-24)

// scratch
__device__ int   g_count[NNODES];                 // in-degree (no self loop)
__device__ int   g_bucket[(size_t)NNODES * BUCKET]; // neighbor lists
__device__ float g_dis[NNODES];                   // (deg+1)^{-1/2}
__device__ float g_bufA[(size_t)NNODES * F_HID];  // GEMM output (pre-aggregate)
__device__ float g_bufB[(size_t)NNODES * F_HID];  // aggregated+activated features
__device__ float g_pool[N_GRAPHS * F_HID];
__device__ float g_cnt[N_GRAPHS];

__device__ __forceinline__ void red_add_v4(float* addr, float4 v) {
    asm volatile("red.global.add.v4.f32 [%0], {%1, %2, %3, %4};"
                 :: "l"(addr), "f"(v.x), "f"(v.y), "f"(v.z), "f"(v.w)
                 : "memory");
}

// ---------------------------------------------------------------------------
// zero counters / pool accumulators
// ---------------------------------------------------------------------------
__global__ void k_zero(int n) {
    int i = blockIdx.x * blockDim.x + threadIdx.x;
    if (i < n) g_count[i] = 0;
    if (i < N_GRAPHS * F_HID) g_pool[i] = 0.0f;
    if (i < N_GRAPHS) g_cnt[i] = 0.0f;
}

// ---------------------------------------------------------------------------
// single-pass bucket fill (histogram + placement in one atomic),
// 4 edges per thread via int4 for MLP
// ---------------------------------------------------------------------------
__global__ void k_fill(const int* __restrict__ src,
                       const int* __restrict__ dst, int nE4) {
    int t = blockIdx.x * blockDim.x + threadIdx.x;
    if (t >= nE4) return;
    int4 s4 = ((const int4*)src)[t];
    int4 d4 = ((const int4*)dst)[t];
    int p0 = atomicAdd(&g_count[d4.x], 1);
    int p1 = atomicAdd(&g_count[d4.y], 1);
    int p2 = atomicAdd(&g_count[d4.z], 1);
    int p3 = atomicAdd(&g_count[d4.w], 1);
    if (p0 < BUCKET) g_bucket[(size_t)d4.x * BUCKET + p0] = s4.x;
    if (p1 < BUCKET) g_bucket[(size_t)d4.y * BUCKET + p1] = s4.y;
    if (p2 < BUCKET) g_bucket[(size_t)d4.z * BUCKET + p2] = s4.z;
    if (p3 < BUCKET) g_bucket[(size_t)d4.w * BUCKET + p3] = s4.w;
}

// ---------------------------------------------------------------------------
// dis = rsqrt(deg+1); graph node counts
// ---------------------------------------------------------------------------
__global__ void k_prep(const int* __restrict__ batch, int n) {
    int i = blockIdx.x * blockDim.x + threadIdx.x;
    if (i >= n) return;
    g_dis[i] = rsqrtf((float)g_count[i] + 1.0f);
    atomicAdd(&g_cnt[batch[i]], 1.0f);
}

// ---------------------------------------------------------------------------
// GEMM: bufA[n,64] = X[n,K] @ W[K,64]
// Block: 256 threads. Tile 256 nodes x 64 cols; thread = 8 nodes x 8 cols.
// ---------------------------------------------------------------------------
template <int K, int KC, bool FROM_BUFB>
__global__ void __launch_bounds__(256) k_gemm(const float* __restrict__ Xin,
                                              const float* __restrict__ W,
                                              int n) {
    __shared__ float Ws[K * 64];
    __shared__ float xs[KC * 256];

    const float* X = FROM_BUFB ? g_bufB : Xin;

    for (int i = threadIdx.x; i < K * 16; i += 256)
        ((float4*)Ws)[i] = ((const float4*)W)[i];

    int nodeBase = blockIdx.x * 256;
    int cg = threadIdx.x & 7;   // 8 cols: 8*cg .. 8*cg+7
    int ng = threadIdx.x >> 3;  // 8 nodes: 8*ng .. 8*ng+7

    float4 acc[8][2];
#pragma unroll
    for (int i = 0; i < 8; i++) {
        acc[i][0] = make_float4(0, 0, 0, 0);
        acc[i][1] = make_float4(0, 0, 0, 0);
    }

    int myNode = nodeBase + threadIdx.x;
    for (int k0 = 0; k0 < K; k0 += KC) {
        __syncthreads();
        if (myNode < n) {
            const float4* Xr = (const float4*)(X + (size_t)myNode * K + k0);
#pragma unroll
            for (int kq = 0; kq < KC / 4; kq++) {
                float4 v = Xr[kq];
                xs[(kq * 4 + 0) * 256 + threadIdx.x] = v.x;
                xs[(kq * 4 + 1) * 256 + threadIdx.x] = v.y;
                xs[(kq * 4 + 2) * 256 + threadIdx.x] = v.z;
                xs[(kq * 4 + 3) * 256 + threadIdx.x] = v.w;
            }
        } else {
#pragma unroll
            for (int kk = 0; kk < KC; kk++)
                xs[kk * 256 + threadIdx.x] = 0.0f;
        }
        __syncthreads();

#pragma unroll
        for (int k = 0; k < KC; k++) {
            const float4* xr = (const float4*)(xs + k * 256);
            float4 xA = xr[ng * 2], xB = xr[ng * 2 + 1];
            const float4* wr = (const float4*)(Ws + (k0 + k) * 64);
            float4 wA = wr[cg * 2], wB = wr[cg * 2 + 1];
            float xv;
#define GEMM_STEP(i, XV)                                                     \
            xv = (XV);                                                       \
            acc[i][0].x = fmaf(xv, wA.x, acc[i][0].x);                       \
            acc[i][0].y = fmaf(xv, wA.y, acc[i][0].y);                       \
            acc[i][0].z = fmaf(xv, wA.z, acc[i][0].z);                       \
            acc[i][0].w = fmaf(xv, wA.w, acc[i][0].w);                       \
            acc[i][1].x = fmaf(xv, wB.x, acc[i][1].x);                       \
            acc[i][1].y = fmaf(xv, wB.y, acc[i][1].y);                       \
            acc[i][1].z = fmaf(xv, wB.z, acc[i][1].z);                       \
            acc[i][1].w = fmaf(xv, wB.w, acc[i][1].w);
            GEMM_STEP(0, xA.x) GEMM_STEP(1, xA.y) GEMM_STEP(2, xA.z) GEMM_STEP(3, xA.w)
            GEMM_STEP(4, xB.x) GEMM_STEP(5, xB.y) GEMM_STEP(6, xB.z) GEMM_STEP(7, xB.w)
#undef GEMM_STEP
        }
    }

#pragma unroll
    for (int i = 0; i < 8; i++) {
        int node = nodeBase + ng * 8 + i;
        if (node < n) {
            float4* out = (float4*)(g_bufA + (size_t)node * 64);
            out[cg * 2 + 0] = acc[i][0];
            out[cg * 2 + 1] = acc[i][1];
        }
    }
}

// ---------------------------------------------------------------------------
// gather core: acc = dis_i * (dis_i*A[i] + sum_s dis_s*A[s])
// 16 threads per node (one float4 lane each), neighbor loop unrolled x4.
// ---------------------------------------------------------------------------
__device__ __forceinline__ float4 gather_node(int i, int q, float di) {
    const float4* A = (const float4*)g_bufA;
    float4 a = A[(size_t)i * 16 + q];
    float4 acc = make_float4(di * a.x, di * a.y, di * a.z, di * a.w);
    int cnt = g_count[i];
    const int* nb = g_bucket + (size_t)i * BUCKET;
    int j = 0;
    for (; j + 4 <= cnt; j += 4) {
        int s0 = nb[j], s1 = nb[j + 1], s2 = nb[j + 2], s3 = nb[j + 3];
        float w0 = g_dis[s0], w1 = g_dis[s1], w2 = g_dis[s2], w3 = g_dis[s3];
        float4 v0 = A[(size_t)s0 * 16 + q];
        float4 v1 = A[(size_t)s1 * 16 + q];
        float4 v2 = A[(size_t)s2 * 16 + q];
        float4 v3 = A[(size_t)s3 * 16 + q];
        acc.x = fmaf(w0, v0.x, acc.x); acc.y = fmaf(w0, v0.y, acc.y);
        acc.z = fmaf(w0, v0.z, acc.z); acc.w = fmaf(w0, v0.w, acc.w);
        acc.x = fmaf(w1, v1.x, acc.x); acc.y = fmaf(w1, v1.y, acc.y);
        acc.z = fmaf(w1, v1.z, acc.z); acc.w = fmaf(w1, v1.w, acc.w);
        acc.x = fmaf(w2, v2.x, acc.x); acc.y = fmaf(w2, v2.y, acc.y);
        acc.z = fmaf(w2, v2.z, acc.z); acc.w = fmaf(w2, v2.w, acc.w);
        acc.x = fmaf(w3, v3.x, acc.x); acc.y = fmaf(w3, v3.y, acc.y);
        acc.z = fmaf(w3, v3.z, acc.z); acc.w = fmaf(w3, v3.w, acc.w);
    }
    for (; j < cnt; j++) {
        int s = nb[j];
        float w = g_dis[s];
        float4 v = A[(size_t)s * 16 + q];
        acc.x = fmaf(w, v.x, acc.x); acc.y = fmaf(w, v.y, acc.y);
        acc.z = fmaf(w, v.z, acc.z); acc.w = fmaf(w, v.w, acc.w);
    }
    acc.x *= di; acc.y *= di; acc.z *= di; acc.w *= di;
    return acc;
}

// gather1: bufB[i] = relu(gather + b1)   (activation fused -> gemm2 reads plain)
__global__ void k_gather1(const float* __restrict__ b1, int n) {
    int idx = blockIdx.x * blockDim.x + threadIdx.x;
    int i = idx >> 4, q = idx & 15;
    if (i >= n) return;
    float4 acc = gather_node(i, q, g_dis[i]);
    float4 bb = ((const float4*)b1)[q];
    acc.x = fmaxf(acc.x + bb.x, 0.0f);
    acc.y = fmaxf(acc.y + bb.y, 0.0f);
    acc.z = fmaxf(acc.z + bb.z, 0.0f);
    acc.w = fmaxf(acc.w + bb.w, 0.0f);
    ((float4*)(g_bufB + (size_t)i * 64))[q] = acc;
}

// gather2 fused with pooling: pool[batch[i]] += relu(gather + b2)
__global__ void k_gather2_pool(const int* __restrict__ batch,
                               const float* __restrict__ b2, int n) {
    int idx = blockIdx.x * blockDim.x + threadIdx.x;
    int i = idx >> 4, q = idx & 15;
    if (i >= n) return;
    float4 acc = gather_node(i, q, g_dis[i]);
    float4 bb = ((const float4*)b2)[q];
    acc.x = fmaxf(acc.x + bb.x, 0.0f);
    acc.y = fmaxf(acc.y + bb.y, 0.0f);
    acc.z = fmaxf(acc.z + bb.z, 0.0f);
    acc.w = fmaxf(acc.w + bb.w, 0.0f);
    int g = batch[i];
    red_add_v4(g_pool + g * 64 + q * 4, acc);
}

__global__ void k_final(const float* __restrict__ Wf, const float* __restrict__ bf,
                        float* __restrict__ out) {
    int t = threadIdx.x;
    if (t >= N_GRAPHS * 2) return;
    int g = t >> 1, c = t & 1;
    float acc = 0.0f;
#pragma unroll
    for (int j = 0; j < F_HID; j++)
        acc = fmaf(g_pool[g * 64 + j], Wf[j * 2 + c], acc);
    float cnt = fmaxf(g_cnt[g], 1.0f);
    out[g * 2 + c] = acc / cnt + bf[c];
}

// ---------------------------------------------------------------------------
extern "C" void kernel_launch(void* const* d_in, const int* in_sizes, int n_in,
                              void* d_out, int out_size) {
    const float* x    = (const float*)d_in[0];
    const int*   ei   = (const int*)d_in[1];  // [2, E] int32
    const int*   batch= (const int*)d_in[2];
    const float* W1   = (const float*)d_in[3];
    const float* b1   = (const float*)d_in[4];
    const float* W2   = (const float*)d_in[5];
    const float* b2   = (const float*)d_in[6];
    const float* Wf   = (const float*)d_in[7];
    const float* bf   = (const float*)d_in[8];
    float* out = (float*)d_out;

    int n  = in_sizes[0] / F_IN;   // 100000
    int nE = in_sizes[1] / 2;      // 1600000 (multiple of 4)
    const int* src = ei;
    const int* dst = ei + nE;

    const int T = 256;
    int gN   = (n + T - 1) / T;
    int nE4  = nE / 4;
    int gE4  = (nE4 + T - 1) / T;
    int gN16 = (int)(((size_t)n * 16 + T - 1) / T);
    int gGemm = (n + 255) / 256;

    // graph structure (bucket CSR, single pass) + normalization
    k_zero<<<gN, T>>>(n);
    k_fill<<<gE4, T>>>(src, dst, nE4);
    k_prep<<<gN, T>>>(batch, n);

    // layer 1
    k_gemm<F_IN, 16, false><<<gGemm, T>>>(x, W1, n);
    k_gather1<<<gN16, T>>>(b1, n);

    // layer 2
    k_gemm<F_HID, 32, true><<<gGemm, T>>>(nullptr, W2, n);
    k_gather2_pool<<<gN16, T>>>(batch, b2, n);

    // classifier
    k_final<<<1, T>>>(Wf, bf, out);
}

// round 6
// speedup vs baseline: 1.2401x; 1.2401x over previous
#include <cuda_runtime.h>
#include <math.h>

#define NNODES   100000
#define NEDGES   1600000
#define F_IN     128
#define F_HID    64
#define N_GRAPHS 128
#define BUCKET   64   // max in-degree capacity (Poisson(16): P(>=64) ~ 1e-24)

typedef unsigned long long ull;

// scratch
__device__ int   g_count[NNODES];                 // in-degree (no self loop)
__device__ int   g_bucket[(size_t)NNODES * BUCKET]; // neighbor lists
__device__ float g_dis[NNODES];                   // (deg+1)^{-1/2}
__device__ float g_bufA[(size_t)NNODES * F_HID];  // GEMM output (pre-aggregate)
__device__ float g_bufB[(size_t)NNODES * F_HID];  // aggregated+activated features
__device__ float g_pool[N_GRAPHS * F_HID];
__device__ float g_cnt[N_GRAPHS];

__device__ __forceinline__ void red_add_v4(float* addr, float4 v) {
    asm volatile("red.global.add.v4.f32 [%0], {%1, %2, %3, %4};"
                 :: "l"(addr), "f"(v.x), "f"(v.y), "f"(v.z), "f"(v.w)
                 : "memory");
}

// packed fp32x2 FMA (sm_103a; FFMA2 in SASS, only reachable via PTX)
#define FFMA2(d, a, b) \
    asm("fma.rn.f32x2 %0, %1, %2, %0;" : "+l"(d) : "l"(a), "l"(b))

__device__ __forceinline__ float2 unpack2(ull v) {
    float2 r;
    asm("mov.b64 {%0, %1}, %2;" : "=f"(r.x), "=f"(r.y) : "l"(v));
    return r;
}

// ---------------------------------------------------------------------------
// zero counters / pool accumulators
// ---------------------------------------------------------------------------
__global__ void k_zero(int n) {
    int i = blockIdx.x * blockDim.x + threadIdx.x;
    if (i < n) g_count[i] = 0;
    if (i < N_GRAPHS * F_HID) g_pool[i] = 0.0f;
    if (i < N_GRAPHS) g_cnt[i] = 0.0f;
}

// ---------------------------------------------------------------------------
// single-pass bucket fill (histogram + placement in one atomic)
// ---------------------------------------------------------------------------
__global__ void k_fill(const int* __restrict__ src,
                       const int* __restrict__ dst, int nE4) {
    int t = blockIdx.x * blockDim.x + threadIdx.x;
    if (t >= nE4) return;
    int4 s4 = ((const int4*)src)[t];
    int4 d4 = ((const int4*)dst)[t];
    int p0 = atomicAdd(&g_count[d4.x], 1);
    int p1 = atomicAdd(&g_count[d4.y], 1);
    int p2 = atomicAdd(&g_count[d4.z], 1);
    int p3 = atomicAdd(&g_count[d4.w], 1);
    if (p0 < BUCKET) g_bucket[(size_t)d4.x * BUCKET + p0] = s4.x;
    if (p1 < BUCKET) g_bucket[(size_t)d4.y * BUCKET + p1] = s4.y;
    if (p2 < BUCKET) g_bucket[(size_t)d4.z * BUCKET + p2] = s4.z;
    if (p3 < BUCKET) g_bucket[(size_t)d4.w * BUCKET + p3] = s4.w;
}

__global__ void k_prep(const int* __restrict__ batch, int n) {
    int i = blockIdx.x * blockDim.x + threadIdx.x;
    if (i >= n) return;
    g_dis[i] = rsqrtf((float)g_count[i] + 1.0f);
    atomicAdd(&g_cnt[batch[i]], 1.0f);
}

// ---------------------------------------------------------------------------
// GEMM via packed f32x2 FMA: bufA[n,64] = X[n,K] @ W[K,64]
// 256 threads; block tile 128 nodes x 64 cols; thread = 4 nodes x 8 cols.
// X tile stored duplicated {v,v} so both FFMA2 operands come straight from LDS.
// ---------------------------------------------------------------------------
template <int K, int KC, bool FROM_BUFB>
__global__ void __launch_bounds__(256) k_gemm(const float* __restrict__ Xin,
                                              const float* __restrict__ W,
                                              int n) {
    __shared__ __align__(16) float Ws[K * 64];
    __shared__ __align__(16) float2 xs2[KC * 128];   // duplicated x values

    const float* X = FROM_BUFB ? g_bufB : Xin;

    for (int i = threadIdx.x; i < K * 16; i += 256)
        ((float4*)Ws)[i] = ((const float4*)W)[i];

    int nodeBase = blockIdx.x * 128;
    int cg = threadIdx.x & 7;    // cols 8*cg .. 8*cg+7
    int ng = threadIdx.x >> 3;   // nodes 4*ng .. 4*ng+3

    ull acc[4][4];
#pragma unroll
    for (int i = 0; i < 4; i++)
#pragma unroll
        for (int j = 0; j < 4; j++) acc[i][j] = 0ULL;

    int nodeLocal = threadIdx.x >> 1;   // 0..127
    int half = threadIdx.x & 1;         // which half of the K-chunk
    int myNode = nodeBase + nodeLocal;

    for (int k0 = 0; k0 < K; k0 += KC) {
        __syncthreads();
        if (myNode < n) {
            const float4* Xr =
                (const float4*)(X + (size_t)myNode * K + k0 + half * (KC / 2));
#pragma unroll
            for (int jq = 0; jq < KC / 8; jq++) {
                float4 v = Xr[jq];
                int kk = half * (KC / 2) + jq * 4;
                xs2[(kk + 0) * 128 + nodeLocal] = make_float2(v.x, v.x);
                xs2[(kk + 1) * 128 + nodeLocal] = make_float2(v.y, v.y);
                xs2[(kk + 2) * 128 + nodeLocal] = make_float2(v.z, v.z);
                xs2[(kk + 3) * 128 + nodeLocal] = make_float2(v.w, v.w);
            }
        } else {
#pragma unroll
            for (int j = 0; j < KC / 2; j++)
                xs2[(half * (KC / 2) + j) * 128 + nodeLocal] = make_float2(0.f, 0.f);
        }
        __syncthreads();

#pragma unroll
        for (int k = 0; k < KC; k++) {
            const ulonglong2* xr = (const ulonglong2*)(xs2 + k * 128);
            ulonglong2 xA = xr[ng * 2];      // nodes 4ng, 4ng+1 (each {v,v})
            ulonglong2 xB = xr[ng * 2 + 1];  // nodes 4ng+2, 4ng+3
            const ulonglong2* wr = (const ulonglong2*)(Ws + (k0 + k) * 64);
            ulonglong2 wA = wr[cg * 2];      // cols 8cg+0..3 packed as 2x f32x2
            ulonglong2 wB = wr[cg * 2 + 1];  // cols 8cg+4..7
            FFMA2(acc[0][0], xA.x, wA.x); FFMA2(acc[0][1], xA.x, wA.y);
            FFMA2(acc[0][2], xA.x, wB.x); FFMA2(acc[0][3], xA.x, wB.y);
            FFMA2(acc[1][0], xA.y, wA.x); FFMA2(acc[1][1], xA.y, wA.y);
            FFMA2(acc[1][2], xA.y, wB.x); FFMA2(acc[1][3], xA.y, wB.y);
            FFMA2(acc[2][0], xB.x, wA.x); FFMA2(acc[2][1], xB.x, wA.y);
            FFMA2(acc[2][2], xB.x, wB.x); FFMA2(acc[2][3], xB.x, wB.y);
            FFMA2(acc[3][0], xB.y, wA.x); FFMA2(acc[3][1], xB.y, wA.y);
            FFMA2(acc[3][2], xB.y, wB.x); FFMA2(acc[3][3], xB.y, wB.y);
        }
    }

#pragma unroll
    for (int i = 0; i < 4; i++) {
        int node = nodeBase + 4 * ng + i;
        if (node < n) {
            float2 p0 = unpack2(acc[i][0]);
            float2 p1 = unpack2(acc[i][1]);
            float2 p2 = unpack2(acc[i][2]);
            float2 p3 = unpack2(acc[i][3]);
            float4* out = (float4*)(g_bufA + (size_t)node * 64);
            out[cg * 2 + 0] = make_float4(p0.x, p0.y, p1.x, p1.y);
            out[cg * 2 + 1] = make_float4(p2.x, p2.y, p3.x, p3.y);
        }
    }
}

// ---------------------------------------------------------------------------
// gather core: acc = dis_i * (dis_i*A[i] + sum_s dis_s*A[s])
// 16 threads per node (one float4 lane each), neighbor loop unrolled x4.
// ---------------------------------------------------------------------------
__device__ __forceinline__ float4 gather_node(int i, int q, float di) {
    const float4* A = (const float4*)g_bufA;
    float4 a = A[(size_t)i * 16 + q];
    float4 acc = make_float4(di * a.x, di * a.y, di * a.z, di * a.w);
    int cnt = g_count[i];
    const int* nb = g_bucket + (size_t)i * BUCKET;
    int j = 0;
    for (; j + 4 <= cnt; j += 4) {
        int s0 = nb[j], s1 = nb[j + 1], s2 = nb[j + 2], s3 = nb[j + 3];
        float w0 = g_dis[s0], w1 = g_dis[s1], w2 = g_dis[s2], w3 = g_dis[s3];
        float4 v0 = A[(size_t)s0 * 16 + q];
        float4 v1 = A[(size_t)s1 * 16 + q];
        float4 v2 = A[(size_t)s2 * 16 + q];
        float4 v3 = A[(size_t)s3 * 16 + q];
        acc.x = fmaf(w0, v0.x, acc.x); acc.y = fmaf(w0, v0.y, acc.y);
        acc.z = fmaf(w0, v0.z, acc.z); acc.w = fmaf(w0, v0.w, acc.w);
        acc.x = fmaf(w1, v1.x, acc.x); acc.y = fmaf(w1, v1.y, acc.y);
        acc.z = fmaf(w1, v1.z, acc.z); acc.w = fmaf(w1, v1.w, acc.w);
        acc.x = fmaf(w2, v2.x, acc.x); acc.y = fmaf(w2, v2.y, acc.y);
        acc.z = fmaf(w2, v2.z, acc.z); acc.w = fmaf(w2, v2.w, acc.w);
        acc.x = fmaf(w3, v3.x, acc.x); acc.y = fmaf(w3, v3.y, acc.y);
        acc.z = fmaf(w3, v3.z, acc.z); acc.w = fmaf(w3, v3.w, acc.w);
    }
    for (; j < cnt; j++) {
        int s = nb[j];
        float w = g_dis[s];
        float4 v = A[(size_t)s * 16 + q];
        acc.x = fmaf(w, v.x, acc.x); acc.y = fmaf(w, v.y, acc.y);
        acc.z = fmaf(w, v.z, acc.z); acc.w = fmaf(w, v.w, acc.w);
    }
    acc.x *= di; acc.y *= di; acc.z *= di; acc.w *= di;
    return acc;
}

// gather1: bufB[i] = relu(gather + b1)   (activation fused -> gemm2 reads plain)
__global__ void k_gather1(const float* __restrict__ b1, int n) {
    int idx = blockIdx.x * blockDim.x + threadIdx.x;
    int i = idx >> 4, q = idx & 15;
    if (i >= n) return;
    float4 acc = gather_node(i, q, g_dis[i]);
    float4 bb = ((const float4*)b1)[q];
    acc.x = fmaxf(acc.x + bb.x, 0.0f);
    acc.y = fmaxf(acc.y + bb.y, 0.0f);
    acc.z = fmaxf(acc.z + bb.z, 0.0f);
    acc.w = fmaxf(acc.w + bb.w, 0.0f);
    ((float4*)(g_bufB + (size_t)i * 64))[q] = acc;
}

// gather2 fused with pooling: pool[batch[i]] += relu(gather + b2)
__global__ void k_gather2_pool(const int* __restrict__ batch,
                               const float* __restrict__ b2, int n) {
    int idx = blockIdx.x * blockDim.x + threadIdx.x;
    int i = idx >> 4, q = idx & 15;
    if (i >= n) return;
    float4 acc = gather_node(i, q, g_dis[i]);
    float4 bb = ((const float4*)b2)[q];
    acc.x = fmaxf(acc.x + bb.x, 0.0f);
    acc.y = fmaxf(acc.y + bb.y, 0.0f);
    acc.z = fmaxf(acc.z + bb.z, 0.0f);
    acc.w = fmaxf(acc.w + bb.w, 0.0f);
    int g = batch[i];
    red_add_v4(g_pool + g * 64 + q * 4, acc);
}

__global__ void k_final(const float* __restrict__ Wf, const float* __restrict__ bf,
                        float* __restrict__ out) {
    int t = threadIdx.x;
    if (t >= N_GRAPHS * 2) return;
    int g = t >> 1, c = t & 1;
    float acc = 0.0f;
#pragma unroll
    for (int j = 0; j < F_HID; j++)
        acc = fmaf(g_pool[g * 64 + j], Wf[j * 2 + c], acc);
    float cnt = fmaxf(g_cnt[g], 1.0f);
    out[g * 2 + c] = acc / cnt + bf[c];
}

// ---------------------------------------------------------------------------
extern "C" void kernel_launch(void* const* d_in, const int* in_sizes, int n_in,
                              void* d_out, int out_size) {
    const float* x    = (const float*)d_in[0];
    const int*   ei   = (const int*)d_in[1];  // [2, E] int32
    const int*   batch= (const int*)d_in[2];
    const float* W1   = (const float*)d_in[3];
    const float* b1   = (const float*)d_in[4];
    const float* W2   = (const float*)d_in[5];
    const float* b2   = (const float*)d_in[6];
    const float* Wf   = (const float*)d_in[7];
    const float* bf   = (const float*)d_in[8];
    float* out = (float*)d_out;

    int n  = in_sizes[0] / F_IN;   // 100000
    int nE = in_sizes[1] / 2;      // 1600000 (multiple of 4)
    const int* src = ei;
    const int* dst = ei + nE;

    const int T = 256;
    int gN   = (n + T - 1) / T;
    int nE4  = nE / 4;
    int gE4  = (nE4 + T - 1) / T;
    int gN16 = (int)(((size_t)n * 16 + T - 1) / T);
    int gGemm = (n + 127) / 128;

    // graph structure (bucket CSR, single pass) + normalization
    k_zero<<<gN, T>>>(n);
    k_fill<<<gE4, T>>>(src, dst, nE4);
    k_prep<<<gN, T>>>(batch, n);

    // layer 1
    k_gemm<F_IN, 16, false><<<gGemm, T>>>(x, W1, n);
    k_gather1<<<gN16, T>>>(b1, n);

    // layer 2
    k_gemm<F_HID, 32, true><<<gGemm, T>>>(nullptr, W2, n);
    k_gather2_pool<<<gN16, T>>>(batch, b2, n);

    // classifier
    k_final<<<1, T>>>(Wf, bf, out);
}

// round 7
// speedup vs baseline: 1.4288x; 1.1522x over previous
#include <cuda_runtime.h>
#include <cuda_fp16.h>
#include <math.h>

#define NNODES   100000
#define NEDGES   1600000
#define F_IN     128
#define F_HID    64
#define N_GRAPHS 128
#define BUCKET   64   // max in-degree capacity (Poisson(16): P(>=64) ~ 1e-24)

typedef unsigned long long ull;

// scratch
__device__ int    g_count[NNODES];                  // in-degree (no self loop)
__device__ int    g_bucket[(size_t)NNODES * BUCKET];// neighbor lists
__device__ float  g_dis[NNODES];                    // (deg+1)^{-1/2}
__device__ __half g_bufAh[(size_t)NNODES * F_HID];  // dis-prescaled GEMM out (fp16)
__device__ float  g_bufB[(size_t)NNODES * F_HID];   // layer-1 activated features
__device__ float  g_pool[N_GRAPHS * F_HID];
__device__ float  g_cnt[N_GRAPHS];

__device__ __forceinline__ void red_add_v4(float* addr, float4 v) {
    asm volatile("red.global.add.v4.f32 [%0], {%1, %2, %3, %4};"
                 :: "l"(addr), "f"(v.x), "f"(v.y), "f"(v.z), "f"(v.w)
                 : "memory");
}

// packed fp32x2 FMA (sm_103a; FFMA2 in SASS, only reachable via PTX)
#define FFMA2(d, a, b) \
    asm("fma.rn.f32x2 %0, %1, %2, %0;" : "+l"(d) : "l"(a), "l"(b))

__device__ __forceinline__ float2 unpack2(ull v) {
    float2 r;
    asm("mov.b64 {%0, %1}, %2;" : "=f"(r.x), "=f"(r.y) : "l"(v));
    return r;
}

// ---------------------------------------------------------------------------
__global__ void k_zero(int n) {
    int i = blockIdx.x * blockDim.x + threadIdx.x;
    if (i < n) g_count[i] = 0;
    if (i < N_GRAPHS * F_HID) g_pool[i] = 0.0f;
    if (i < N_GRAPHS) g_cnt[i] = 0.0f;
}

// single-pass bucket fill (histogram + placement in one atomic)
__global__ void k_fill(const int* __restrict__ src,
                       const int* __restrict__ dst, int nE4) {
    int t = blockIdx.x * blockDim.x + threadIdx.x;
    if (t >= nE4) return;
    int4 s4 = ((const int4*)src)[t];
    int4 d4 = ((const int4*)dst)[t];
    int p0 = atomicAdd(&g_count[d4.x], 1);
    int p1 = atomicAdd(&g_count[d4.y], 1);
    int p2 = atomicAdd(&g_count[d4.z], 1);
    int p3 = atomicAdd(&g_count[d4.w], 1);
    if (p0 < BUCKET) g_bucket[(size_t)d4.x * BUCKET + p0] = s4.x;
    if (p1 < BUCKET) g_bucket[(size_t)d4.y * BUCKET + p1] = s4.y;
    if (p2 < BUCKET) g_bucket[(size_t)d4.z * BUCKET + p2] = s4.z;
    if (p3 < BUCKET) g_bucket[(size_t)d4.w * BUCKET + p3] = s4.w;
}

__global__ void k_prep(const int* __restrict__ batch, int n) {
    int i = blockIdx.x * blockDim.x + threadIdx.x;
    if (i >= n) return;
    g_dis[i] = rsqrtf((float)g_count[i] + 1.0f);
    atomicAdd(&g_cnt[batch[i]], 1.0f);
}

// ---------------------------------------------------------------------------
// GEMM via packed f32x2 FMA: bufAh[n,64] = fp16( dis * (X[n,K] @ W[K,64]) )
// 256 threads; block tile 128 nodes x 64 cols; thread = 4 nodes x 8 cols.
// X chunks prefetched into registers so global latency overlaps compute.
// ---------------------------------------------------------------------------
template <int K, int KC, bool FROM_BUFB>
__global__ void __launch_bounds__(256) k_gemm(const float* __restrict__ Xin,
                                              const float* __restrict__ W,
                                              int n) {
    __shared__ __align__(16) float Ws[K * 64];
    __shared__ __align__(16) float2 xs2[KC * 128];   // duplicated {v,v} x values

    const float* X = FROM_BUFB ? g_bufB : Xin;

    for (int i = threadIdx.x; i < K * 16; i += 256)
        ((float4*)Ws)[i] = ((const float4*)W)[i];

    int nodeBase = blockIdx.x * 128;
    int cg = threadIdx.x & 7;    // cols 8*cg .. 8*cg+7
    int ng = threadIdx.x >> 3;   // nodes 4*ng .. 4*ng+3

    ull acc[4][4];
#pragma unroll
    for (int i = 0; i < 4; i++)
#pragma unroll
        for (int j = 0; j < 4; j++) acc[i][j] = 0ULL;

    int nodeLocal = threadIdx.x >> 1;   // 0..127
    int half = threadIdx.x & 1;         // which half of the K-chunk
    int myNode = nodeBase + nodeLocal;
    const float* Xrow = X + (size_t)myNode * K + half * (KC / 2);

    float4 pre[KC / 8];
    // prefetch chunk 0
#pragma unroll
    for (int jq = 0; jq < KC / 8; jq++)
        pre[jq] = (myNode < n) ? ((const float4*)Xrow)[jq]
                               : make_float4(0, 0, 0, 0);

    for (int k0 = 0; k0 < K; k0 += KC) {
        __syncthreads();   // consumers finished with xs2 from previous chunk
#pragma unroll
        for (int jq = 0; jq < KC / 8; jq++) {
            float4 v = pre[jq];
            int kk = half * (KC / 2) + jq * 4;
            xs2[(kk + 0) * 128 + nodeLocal] = make_float2(v.x, v.x);
            xs2[(kk + 1) * 128 + nodeLocal] = make_float2(v.y, v.y);
            xs2[(kk + 2) * 128 + nodeLocal] = make_float2(v.z, v.z);
            xs2[(kk + 3) * 128 + nodeLocal] = make_float2(v.w, v.w);
        }
        __syncthreads();

        // prefetch next chunk (latency overlaps the FFMA2 block below)
        if (k0 + KC < K) {
            const float4* Xn = (const float4*)(Xrow + k0 + KC);
#pragma unroll
            for (int jq = 0; jq < KC / 8; jq++)
                pre[jq] = (myNode < n) ? Xn[jq] : make_float4(0, 0, 0, 0);
        }

#pragma unroll
        for (int k = 0; k < KC; k++) {
            const ulonglong2* xr = (const ulonglong2*)(xs2 + k * 128);
            ulonglong2 xA = xr[ng * 2];      // nodes 4ng, 4ng+1 (each {v,v})
            ulonglong2 xB = xr[ng * 2 + 1];  // nodes 4ng+2, 4ng+3
            const ulonglong2* wr = (const ulonglong2*)(Ws + (k0 + k) * 64);
            ulonglong2 wA = wr[cg * 2];
            ulonglong2 wB = wr[cg * 2 + 1];
            FFMA2(acc[0][0], xA.x, wA.x); FFMA2(acc[0][1], xA.x, wA.y);
            FFMA2(acc[0][2], xA.x, wB.x); FFMA2(acc[0][3], xA.x, wB.y);
            FFMA2(acc[1][0], xA.y, wA.x); FFMA2(acc[1][1], xA.y, wA.y);
            FFMA2(acc[1][2], xA.y, wB.x); FFMA2(acc[1][3], xA.y, wB.y);
            FFMA2(acc[2][0], xB.x, wA.x); FFMA2(acc[2][1], xB.x, wA.y);
            FFMA2(acc[2][2], xB.x, wB.x); FFMA2(acc[2][3], xB.x, wB.y);
            FFMA2(acc[3][0], xB.y, wA.x); FFMA2(acc[3][1], xB.y, wA.y);
            FFMA2(acc[3][2], xB.y, wB.x); FFMA2(acc[3][3], xB.y, wB.y);
        }
    }

    // epilogue: scale by dis[node], convert to fp16, 16B store per node
#pragma unroll
    for (int i = 0; i < 4; i++) {
        int node = nodeBase + 4 * ng + i;
        if (node < n) {
            float d = g_dis[node];
            float2 p0 = unpack2(acc[i][0]);
            float2 p1 = unpack2(acc[i][1]);
            float2 p2 = unpack2(acc[i][2]);
            float2 p3 = unpack2(acc[i][3]);
            __half2 h0 = __floats2half2_rn(p0.x * d, p0.y * d);
            __half2 h1 = __floats2half2_rn(p1.x * d, p1.y * d);
            __half2 h2 = __floats2half2_rn(p2.x * d, p2.y * d);
            __half2 h3 = __floats2half2_rn(p3.x * d, p3.y * d);
            uint4 st;
            st.x = *(unsigned*)&h0; st.y = *(unsigned*)&h1;
            st.z = *(unsigned*)&h2; st.w = *(unsigned*)&h3;
            ((uint4*)(g_bufAh + (size_t)node * 64))[cg] = st;
        }
    }
}

// ---------------------------------------------------------------------------
// gather core on dis-prescaled fp16 features:
//   out_i = dis_i * ( scaled[i] + sum_s scaled[s] )
// 16 threads per node (4 cols each as uint2), neighbor loop unrolled x4.
// ---------------------------------------------------------------------------
__device__ __forceinline__ float4 cvt4(uint2 u) {
    float2 lo = __half22float2(*(__half2*)&u.x);
    float2 hi = __half22float2(*(__half2*)&u.y);
    return make_float4(lo.x, lo.y, hi.x, hi.y);
}

__device__ __forceinline__ float4 gather_node(int i, int q) {
    const uint2* A = (const uint2*)g_bufAh;   // row = 16 x 8B
    float4 acc = cvt4(A[(size_t)i * 16 + q]); // self term (already dis_i-scaled)
    int cnt = min(g_count[i], BUCKET);
    const int* nb = g_bucket + (size_t)i * BUCKET;
    int j = 0;
    for (; j + 4 <= cnt; j += 4) {
        int s0 = nb[j], s1 = nb[j + 1], s2 = nb[j + 2], s3 = nb[j + 3];
        uint2 u0 = A[(size_t)s0 * 16 + q];
        uint2 u1 = A[(size_t)s1 * 16 + q];
        uint2 u2 = A[(size_t)s2 * 16 + q];
        uint2 u3 = A[(size_t)s3 * 16 + q];
        float4 v0 = cvt4(u0), v1 = cvt4(u1), v2 = cvt4(u2), v3 = cvt4(u3);
        acc.x += v0.x + v1.x + v2.x + v3.x;
        acc.y += v0.y + v1.y + v2.y + v3.y;
        acc.z += v0.z + v1.z + v2.z + v3.z;
        acc.w += v0.w + v1.w + v2.w + v3.w;
    }
    for (; j < cnt; j++) {
        float4 v = cvt4(A[(size_t)nb[j] * 16 + q]);
        acc.x += v.x; acc.y += v.y; acc.z += v.z; acc.w += v.w;
    }
    float di = g_dis[i];
    acc.x *= di; acc.y *= di; acc.z *= di; acc.w *= di;
    return acc;
}

// gather1: bufB[i] = relu(gather + b1)  (fp32; GEMM2 input)
__global__ void k_gather1(const float* __restrict__ b1, int n) {
    int idx = blockIdx.x * blockDim.x + threadIdx.x;
    int i = idx >> 4, q = idx & 15;
    if (i >= n) return;
    float4 acc = gather_node(i, q);
    float4 bb = ((const float4*)b1)[q];
    acc.x = fmaxf(acc.x + bb.x, 0.0f);
    acc.y = fmaxf(acc.y + bb.y, 0.0f);
    acc.z = fmaxf(acc.z + bb.z, 0.0f);
    acc.w = fmaxf(acc.w + bb.w, 0.0f);
    ((float4*)(g_bufB + (size_t)i * 64))[q] = acc;
}

// gather2 fused with pooling: pool[batch[i]] += relu(gather + b2)
__global__ void k_gather2_pool(const int* __restrict__ batch,
                               const float* __restrict__ b2, int n) {
    int idx = blockIdx.x * blockDim.x + threadIdx.x;
    int i = idx >> 4, q = idx & 15;
    if (i >= n) return;
    float4 acc = gather_node(i, q);
    float4 bb = ((const float4*)b2)[q];
    acc.x = fmaxf(acc.x + bb.x, 0.0f);
    acc.y = fmaxf(acc.y + bb.y, 0.0f);
    acc.z = fmaxf(acc.z + bb.z, 0.0f);
    acc.w = fmaxf(acc.w + bb.w, 0.0f);
    int g = batch[i];
    red_add_v4(g_pool + g * 64 + q * 4, acc);
}

__global__ void k_final(const float* __restrict__ Wf, const float* __restrict__ bf,
                        float* __restrict__ out) {
    int t = threadIdx.x;
    if (t >= N_GRAPHS * 2) return;
    int g = t >> 1, c = t & 1;
    float acc = 0.0f;
#pragma unroll
    for (int j = 0; j < F_HID; j++)
        acc = fmaf(g_pool[g * 64 + j], Wf[j * 2 + c], acc);
    float cnt = fmaxf(g_cnt[g], 1.0f);
    out[g * 2 + c] = acc / cnt + bf[c];
}

// ---------------------------------------------------------------------------
extern "C" void kernel_launch(void* const* d_in, const int* in_sizes, int n_in,
                              void* d_out, int out_size) {
    const float* x    = (const float*)d_in[0];
    const int*   ei   = (const int*)d_in[1];  // [2, E] int32
    const int*   batch= (const int*)d_in[2];
    const float* W1   = (const float*)d_in[3];
    const float* b1   = (const float*)d_in[4];
    const float* W2   = (const float*)d_in[5];
    const float* b2   = (const float*)d_in[6];
    const float* Wf   = (const float*)d_in[7];
    const float* bf   = (const float*)d_in[8];
    float* out = (float*)d_out;

    int n  = in_sizes[0] / F_IN;   // 100000
    int nE = in_sizes[1] / 2;      // 1600000 (multiple of 4)
    const int* src = ei;
    const int* dst = ei + nE;

    const int T = 256;
    int gN   = (n + T - 1) / T;
    int nE4  = nE / 4;
    int gE4  = (nE4 + T - 1) / T;
    int gN16 = (int)(((size_t)n * 16 + T - 1) / T);
    int gGemm = (n + 127) / 128;

    // graph structure (bucket CSR, single pass) + normalization
    k_zero<<<gN, T>>>(n);
    k_fill<<<gE4, T>>>(src, dst, nE4);
    k_prep<<<gN, T>>>(batch, n);

    // layer 1
    k_gemm<F_IN, 16, false><<<gGemm, T>>>(x, W1, n);
    k_gather1<<<gN16, T>>>(b1, n);

    // layer 2
    k_gemm<F_HID, 16, true><<<gGemm, T>>>(nullptr, W2, n);
    k_gather2_pool<<<gN16, T>>>(batch, b2, n);

    // classifier
    k_final<<<1, T>>>(Wf, bf, out);
}

// round 8
// speedup vs baseline: 2.0469x; 1.4326x over previous
#include <cuda_runtime.h>
#include <cuda_fp16.h>
#include <math.h>

#define NNODES   100000
#define NEDGES   1600000
#define F_IN     128
#define F_HID    64
#define N_GRAPHS 128
#define BUCKET   64   // max in-degree capacity (Poisson(16): P(>=64) ~ 1e-24)

// scratch
__device__ int    g_count[NNODES];                  // in-degree (no self loop)
__device__ int    g_bucket[(size_t)NNODES * BUCKET];// neighbor lists
__device__ float  g_dis[NNODES];                    // (deg+1)^{-1/2}
__device__ __half g_bufAh[(size_t)NNODES * F_HID];  // dis-prescaled GEMM out (fp16)
__device__ __half g_bufBh[(size_t)NNODES * F_HID];  // layer-1 activated feats (fp16)
__device__ float  g_pool[N_GRAPHS * F_HID];
__device__ float  g_cnt[N_GRAPHS];

__device__ __forceinline__ void red_add_v4(float* addr, float4 v) {
    asm volatile("red.global.add.v4.f32 [%0], {%1, %2, %3, %4};"
                 :: "l"(addr), "f"(v.x), "f"(v.y), "f"(v.z), "f"(v.w)
                 : "memory");
}

// ---------------------------------------------------------------------------
__global__ void k_zero(int n) {
    int i = blockIdx.x * blockDim.x + threadIdx.x;
    if (i < n) g_count[i] = 0;
    if (i < N_GRAPHS * F_HID) g_pool[i] = 0.0f;
    if (i < N_GRAPHS) g_cnt[i] = 0.0f;
}

// single-pass bucket fill (histogram + placement in one atomic)
__global__ void k_fill(const int* __restrict__ src,
                       const int* __restrict__ dst, int nE4) {
    int t = blockIdx.x * blockDim.x + threadIdx.x;
    if (t >= nE4) return;
    int4 s4 = ((const int4*)src)[t];
    int4 d4 = ((const int4*)dst)[t];
    int p0 = atomicAdd(&g_count[d4.x], 1);
    int p1 = atomicAdd(&g_count[d4.y], 1);
    int p2 = atomicAdd(&g_count[d4.z], 1);
    int p3 = atomicAdd(&g_count[d4.w], 1);
    if (p0 < BUCKET) g_bucket[(size_t)d4.x * BUCKET + p0] = s4.x;
    if (p1 < BUCKET) g_bucket[(size_t)d4.y * BUCKET + p1] = s4.y;
    if (p2 < BUCKET) g_bucket[(size_t)d4.z * BUCKET + p2] = s4.z;
    if (p3 < BUCKET) g_bucket[(size_t)d4.w * BUCKET + p3] = s4.w;
}

__global__ void k_prep(const int* __restrict__ batch, int n) {
    int i = blockIdx.x * blockDim.x + threadIdx.x;
    if (i >= n) return;
    g_dis[i] = rsqrtf((float)g_count[i] + 1.0f);
    atomicAdd(&g_cnt[batch[i]], 1.0f);
}

// ---------------------------------------------------------------------------
// Tensor-core GEMM: bufAh[n,64] = fp16( dis * (X[n,K] @ W[K,64]) )
// mma.sync.m16n8k16 f32.f16.f16.f32. 256 threads = 8 warps; tile 128 nodes.
// Warp w computes nodes w*16..w*16+15 x all 64 cols (8 n-tiles).
// Smem strides chosen so row -> bank-group 4*gid: all fragment LDS conflict-free.
// ---------------------------------------------------------------------------
template <int K, bool FROM_HALF>
__global__ void __launch_bounds__(256) k_gemm_mma(const float* __restrict__ Xf,
                                                  const float* __restrict__ W,
                                                  int n) {
    constexpr int KC = 64;        // k-chunk staged in smem
    constexpr int XP = KC + 8;    // Xs row stride (halves): 72 -> 36 words == 4 mod 32
    constexpr int WP = K + 8;     // Ws row stride (halves): 136/72 -> == 4 mod 32
    __shared__ __half Ws[64 * WP];   // W transposed: Ws[nCol][k]
    __shared__ __half Xs[128 * XP];  // X chunk: Xs[node][k - k0]

    int tid = threadIdx.x;

    // W [K][64] fp32 -> Ws[n][k] fp16 (one-time transpose)
    for (int i = tid; i < K * 64; i += 256) {
        int k = i >> 6, nn = i & 63;
        Ws[nn * WP + k] = __float2half(W[i]);
    }

    int nodeBase = blockIdx.x * 128;
    int warp = tid >> 5, lane = tid & 31;
    int gid = lane >> 2, tg = lane & 3;

    float c[8][4];
#pragma unroll
    for (int i = 0; i < 8; i++)
#pragma unroll
        for (int j = 0; j < 4; j++) c[i][j] = 0.0f;

    for (int k0 = 0; k0 < K; k0 += KC) {
        __syncthreads();
        // stage X chunk (rows 0..127, cols k0..k0+63) as fp16
        for (int i = tid; i < 128 * 16; i += 256) {
            int r = i >> 4, cq = i & 15;   // cq indexes 4-col groups
            int node = nodeBase + r;
            uint2 st = make_uint2(0u, 0u);
            if (node < n) {
                if (FROM_HALF) {
                    st = ((const uint2*)(g_bufBh + (size_t)node * 64 + k0))[cq];
                } else {
                    float4 v = *(const float4*)(Xf + (size_t)node * K + k0 + cq * 4);
                    __half2 h0 = __floats2half2_rn(v.x, v.y);
                    __half2 h1 = __floats2half2_rn(v.z, v.w);
                    st.x = *(unsigned*)&h0;
                    st.y = *(unsigned*)&h1;
                }
            }
            *(uint2*)&Xs[r * XP + cq * 4] = st;
        }
        __syncthreads();

#pragma unroll
        for (int kt = 0; kt < KC / 16; kt++) {
            int kk = kt * 16;
            const __half* ar0 = &Xs[(warp * 16 + gid) * XP + kk + tg * 2];
            const __half* ar1 = ar0 + 8 * XP;
            unsigned a0 = *(const unsigned*)ar0;        // (row,   k..k+1)
            unsigned a1 = *(const unsigned*)ar1;        // (row+8, k..k+1)
            unsigned a2 = *(const unsigned*)(ar0 + 8);  // (row,   k+8..k+9)
            unsigned a3 = *(const unsigned*)(ar1 + 8);  // (row+8, k+8..k+9)
#pragma unroll
            for (int nt = 0; nt < 8; nt++) {
                const __half* br = &Ws[(nt * 8 + gid) * WP + k0 + kk + tg * 2];
                unsigned b0 = *(const unsigned*)br;
                unsigned b1 = *(const unsigned*)(br + 8);
                asm volatile(
                    "mma.sync.aligned.m16n8k16.row.col.f32.f16.f16.f32 "
                    "{%0,%1,%2,%3}, {%4,%5,%6,%7}, {%8,%9}, {%0,%1,%2,%3};"
                    : "+f"(c[nt][0]), "+f"(c[nt][1]),
                      "+f"(c[nt][2]), "+f"(c[nt][3])
                    : "r"(a0), "r"(a1), "r"(a2), "r"(a3), "r"(b0), "r"(b1));
            }
        }
    }

    // epilogue: scale by dis, store fp16 (dis-prescaled for gather)
    int node0 = nodeBase + warp * 16 + gid;
    int node1 = node0 + 8;
    if (node0 < n) {
        float d = g_dis[node0];
#pragma unroll
        for (int nt = 0; nt < 8; nt++) {
            __half2 h = __floats2half2_rn(c[nt][0] * d, c[nt][1] * d);
            *(__half2*)&g_bufAh[(size_t)node0 * 64 + nt * 8 + tg * 2] = h;
        }
    }
    if (node1 < n) {
        float d = g_dis[node1];
#pragma unroll
        for (int nt = 0; nt < 8; nt++) {
            __half2 h = __floats2half2_rn(c[nt][2] * d, c[nt][3] * d);
            *(__half2*)&g_bufAh[(size_t)node1 * 64 + nt * 8 + tg * 2] = h;
        }
    }
}

// ---------------------------------------------------------------------------
// gather core on dis-prescaled fp16 features:
//   out_i = dis_i * ( scaled[i] + sum_s scaled[s] )
// 16 threads per node (4 cols each as uint2), neighbor loop unrolled x4.
// ---------------------------------------------------------------------------
__device__ __forceinline__ float4 cvt4(uint2 u) {
    float2 lo = __half22float2(*(__half2*)&u.x);
    float2 hi = __half22float2(*(__half2*)&u.y);
    return make_float4(lo.x, lo.y, hi.x, hi.y);
}

__device__ __forceinline__ float4 gather_node(int i, int q) {
    const uint2* A = (const uint2*)g_bufAh;   // row = 16 x 8B
    float4 acc = cvt4(A[(size_t)i * 16 + q]); // self term (already dis_i-scaled)
    int cnt = min(g_count[i], BUCKET);
    const int* nb = g_bucket + (size_t)i * BUCKET;
    int j = 0;
    for (; j + 4 <= cnt; j += 4) {
        int s0 = nb[j], s1 = nb[j + 1], s2 = nb[j + 2], s3 = nb[j + 3];
        uint2 u0 = A[(size_t)s0 * 16 + q];
        uint2 u1 = A[(size_t)s1 * 16 + q];
        uint2 u2 = A[(size_t)s2 * 16 + q];
        uint2 u3 = A[(size_t)s3 * 16 + q];
        float4 v0 = cvt4(u0), v1 = cvt4(u1), v2 = cvt4(u2), v3 = cvt4(u3);
        acc.x += v0.x + v1.x + v2.x + v3.x;
        acc.y += v0.y + v1.y + v2.y + v3.y;
        acc.z += v0.z + v1.z + v2.z + v3.z;
        acc.w += v0.w + v1.w + v2.w + v3.w;
    }
    for (; j < cnt; j++) {
        float4 v = cvt4(A[(size_t)nb[j] * 16 + q]);
        acc.x += v.x; acc.y += v.y; acc.z += v.z; acc.w += v.w;
    }
    float di = g_dis[i];
    acc.x *= di; acc.y *= di; acc.z *= di; acc.w *= di;
    return acc;
}

// gather1: bufBh[i] = fp16(relu(gather + b1))   (GEMM2 input, fp16)
__global__ void k_gather1(const float* __restrict__ b1, int n) {
    int idx = blockIdx.x * blockDim.x + threadIdx.x;
    int i = idx >> 4, q = idx & 15;
    if (i >= n) return;
    float4 acc = gather_node(i, q);
    float4 bb = ((const float4*)b1)[q];
    acc.x = fmaxf(acc.x + bb.x, 0.0f);
    acc.y = fmaxf(acc.y + bb.y, 0.0f);
    acc.z = fmaxf(acc.z + bb.z, 0.0f);
    acc.w = fmaxf(acc.w + bb.w, 0.0f);
    __half2 h0 = __floats2half2_rn(acc.x, acc.y);
    __half2 h1 = __floats2half2_rn(acc.z, acc.w);
    uint2 st; st.x = *(unsigned*)&h0; st.y = *(unsigned*)&h1;
    ((uint2*)(g_bufBh + (size_t)i * 64))[q] = st;
}

// gather2 fused with pooling: pool[batch[i]] += relu(gather + b2)
__global__ void k_gather2_pool(const int* __restrict__ batch,
                               const float* __restrict__ b2, int n) {
    int idx = blockIdx.x * blockDim.x + threadIdx.x;
    int i = idx >> 4, q = idx & 15;
    if (i >= n) return;
    float4 acc = gather_node(i, q);
    float4 bb = ((const float4*)b2)[q];
    acc.x = fmaxf(acc.x + bb.x, 0.0f);
    acc.y = fmaxf(acc.y + bb.y, 0.0f);
    acc.z = fmaxf(acc.z + bb.z, 0.0f);
    acc.w = fmaxf(acc.w + bb.w, 0.0f);
    int g = batch[i];
    red_add_v4(g_pool + g * 64 + q * 4, acc);
}

__global__ void k_final(const float* __restrict__ Wf, const float* __restrict__ bf,
                        float* __restrict__ out) {
    int t = threadIdx.x;
    if (t >= N_GRAPHS * 2) return;
    int g = t >> 1, c = t & 1;
    float acc = 0.0f;
#pragma unroll
    for (int j = 0; j < F_HID; j++)
        acc = fmaf(g_pool[g * 64 + j], Wf[j * 2 + c], acc);
    float cnt = fmaxf(g_cnt[g], 1.0f);
    out[g * 2 + c] = acc / cnt + bf[c];
}

// ---------------------------------------------------------------------------
extern "C" void kernel_launch(void* const* d_in, const int* in_sizes, int n_in,
                              void* d_out, int out_size) {
    const float* x    = (const float*)d_in[0];
    const int*   ei   = (const int*)d_in[1];  // [2, E] int32
    const int*   batch= (const int*)d_in[2];
    const float* W1   = (const float*)d_in[3];
    const float* b1   = (const float*)d_in[4];
    const float* W2   = (const float*)d_in[5];
    const float* b2   = (const float*)d_in[6];
    const float* Wf   = (const float*)d_in[7];
    const float* bf   = (const float*)d_in[8];
    float* out = (float*)d_out;

    int n  = in_sizes[0] / F_IN;   // 100000
    int nE = in_sizes[1] / 2;      // 1600000 (multiple of 4)
    const int* src = ei;
    const int* dst = ei + nE;

    const int T = 256;
    int gN   = (n + T - 1) / T;
    int nE4  = nE / 4;
    int gE4  = (nE4 + T - 1) / T;
    int gN16 = (int)(((size_t)n * 16 + T - 1) / T);
    int gGemm = (n + 127) / 128;

    // graph structure (bucket CSR, single pass) + normalization
    k_zero<<<gN, T>>>(n);
    k_fill<<<gE4, T>>>(src, dst, nE4);
    k_prep<<<gN, T>>>(batch, n);

    // layer 1 (tensor-core GEMM, fp32 X input)
    k_gemm_mma<F_IN, false><<<gGemm, T>>>(x, W1, n);
    k_gather1<<<gN16, T>>>(b1, n);

    // layer 2 (tensor-core GEMM, fp16 input from gather1)
    k_gemm_mma<F_HID, true><<<gGemm, T>>>(nullptr, W2, n);
    k_gather2_pool<<<gN16, T>>>(batch, b2, n);

    // classifier
    k_final<<<1, T>>>(Wf, bf, out);
}